// round 16
// baseline (speedup 1.0000x reference)
#include <cuda_runtime.h>

#define IN_FEATURES 8192
#define OUT_FEATURES 8192
#define THREADS 128
#define NWARPS (THREADS / 32)                 // 4
#define F4_PER_ROW (IN_FEATURES / 4)          // 2048
#define F4_PER_THREAD (F4_PER_ROW / THREADS)  // 16

__global__ __launch_bounds__(THREADS)
void snn_fused_kernel(const float* __restrict__ x,
                      const float* __restrict__ states,
                      const float* __restrict__ mp,
                      const float* __restrict__ thr,
                      const float* __restrict__ trace,
                      float* __restrict__ out) {
    __shared__ float4 sx[F4_PER_ROW];   // 32 KB staged spike input
    __shared__ float warp_dot[NWARPS];
    __shared__ float warp_wsum[NWARPS];

    const int o   = blockIdx.x;
    const int tid = threadIdx.x;

    // Hoist scalar epilogue inputs (independent loads; ptxas won't hoist
    // them across the BAR.SYNC if left in the epilogue).
    const float mp_o  = __ldg(&mp[o]);
    const float thr_o = __ldg(&thr[o]);

    // Stage x into shared memory (L2-resident broadcast).
    const float4* x4 = reinterpret_cast<const float4*>(x);
    #pragma unroll
    for (int j = 0; j < F4_PER_THREAD; j++) {
        sx[tid + j * THREADS] = x4[tid + j * THREADS];
    }
    __syncthreads();

    // ---- Phase 1: binary-weight dot product + connection count ----
    // 16 independent float4 loads per thread: deep batching window.
    const float4* st4 = reinterpret_cast<const float4*>(states + (size_t)o * IN_FEATURES);
    float dot = 0.0f, wsum = 0.0f;
    #pragma unroll
    for (int j = 0; j < F4_PER_THREAD; j++) {
        const int i = tid + j * THREADS;
        float4 s  = st4[i];
        float4 xv = sx[i];
        float w0 = (s.x > 50.0f) ? 1.0f : 0.0f;
        float w1 = (s.y > 50.0f) ? 1.0f : 0.0f;
        float w2 = (s.z > 50.0f) ? 1.0f : 0.0f;
        float w3 = (s.w > 50.0f) ? 1.0f : 0.0f;
        dot  += w0 * xv.x + w1 * xv.y + w2 * xv.z + w3 * xv.w;
        wsum += w0 + w1 + w2 + w3;
    }

    // Warp reduce
    #pragma unroll
    for (int off = 16; off > 0; off >>= 1) {
        dot  += __shfl_xor_sync(0xFFFFFFFFu, dot,  off);
        wsum += __shfl_xor_sync(0xFFFFFFFFu, wsum, off);
    }
    const int lane = tid & 31;
    const int wid  = tid >> 5;
    if (lane == 0) { warp_dot[wid] = dot; warp_wsum[wid] = wsum; }
    __syncthreads();   // the single barrier: partials published

    // All-thread redundant final reduce + epilogue (pure smem + ALU).
    float d = 0.0f, ws = 0.0f;
    #pragma unroll
    for (int w = 0; w < NWARPS; w++) { d += warp_dot[w]; ws += warp_wsum[w]; }
    const float conn    = fmaxf(ws, 5.0f);
    const float current = d * (15.0f * rsqrtf(conn));
    const float v_mem   = mp_o * 0.85f + current;
    const float spike   = (v_mem >= thr_o) ? 1.0f : 0.0f;
    if (tid == 0) {
        const float new_v = v_mem * (1.0f - spike) * 0.1f;
        const float new_t = fminf(fmaxf(thr_o + (spike - 0.1f) * 0.1f, 2.0f), 15.0f);
        out[o]                    = spike;   // spikes
        out[OUT_FEATURES + o]     = new_v;   // new membrane potential
        out[2 * OUT_FEATURES + o] = new_t;   // new adaptive threshold
    }

    // ---- Phase 2: eligibility-trace update ----
    const float4* tr4 = reinterpret_cast<const float4*>(trace + (size_t)o * IN_FEATURES);
    float4* ot4 = reinterpret_cast<float4*>(out + 3 * (size_t)OUT_FEATURES + (size_t)o * IN_FEATURES);
    #pragma unroll
    for (int j = 0; j < F4_PER_THREAD; j++) {
        const int i = tid + j * THREADS;
        float4 t  = tr4[i];
        float4 xv = sx[i];
        float4 r;
        r.x = fminf(fmaxf(t.x * 0.9f + spike * xv.x, 0.0f), 5.0f);
        r.y = fminf(fmaxf(t.y * 0.9f + spike * xv.y, 0.0f), 5.0f);
        r.z = fminf(fmaxf(t.z * 0.9f + spike * xv.z, 0.0f), 5.0f);
        r.w = fminf(fmaxf(t.w * 0.9f + spike * xv.w, 0.0f), 5.0f);
        __stcs(&ot4[i], r);
    }
}

extern "C" void kernel_launch(void* const* d_in, const int* in_sizes, int n_in,
                              void* d_out, int out_size) {
    const float* x      = (const float*)d_in[0];   // spike_input [8192]
    const float* states = (const float*)d_in[1];   // synapse_states [8192,8192]
    const float* mp     = (const float*)d_in[2];   // membrane_potential [8192]
    const float* thr    = (const float*)d_in[3];   // adaptive_threshold [8192]
    const float* trace  = (const float*)d_in[4];   // eligibility_trace [8192,8192]
    float* out          = (float*)d_out;

    snn_fused_kernel<<<OUT_FEATURES, THREADS>>>(x, states, mp, thr, trace, out);
}

// round 17
// speedup vs baseline: 1.2301x; 1.2301x over previous
#include <cuda_runtime.h>

#define IN_FEATURES 8192
#define OUT_FEATURES 8192
#define THREADS 256
#define NWARPS (THREADS / 32)
#define F4_PER_ROW (IN_FEATURES / 4)          // 2048
#define F4_PER_THREAD (F4_PER_ROW / THREADS)  // 8

__global__ __launch_bounds__(THREADS, 2)
void snn_fused_kernel(const float* __restrict__ x,
                      const float* __restrict__ states,
                      const float* __restrict__ mp,
                      const float* __restrict__ thr,
                      const float* __restrict__ trace,
                      float* __restrict__ out) {
    __shared__ float4 sx[F4_PER_ROW];   // 32 KB staged spike input
    __shared__ float warp_dot[NWARPS];
    __shared__ float warp_wsum[NWARPS];

    const int o   = blockIdx.x;
    const int tid = threadIdx.x;

    // Hoist the two scalar epilogue inputs to the very top: independent of
    // all other work; ptxas will not hoist them across the BAR.SYNC itself.
    const float mp_o  = __ldg(&mp[o]);
    const float thr_o = __ldg(&thr[o]);

    // Stage x into shared memory (L2-resident broadcast).
    const float4* x4 = reinterpret_cast<const float4*>(x);
    #pragma unroll
    for (int j = 0; j < F4_PER_THREAD; j++) {
        sx[tid + j * THREADS] = x4[tid + j * THREADS];
    }
    __syncthreads();

    // ---- Phase 1: binary-weight dot product + connection count ----
    const float4* st4 = reinterpret_cast<const float4*>(states + (size_t)o * IN_FEATURES);
    float dot = 0.0f, wsum = 0.0f;
    #pragma unroll
    for (int j = 0; j < F4_PER_THREAD; j++) {
        const int i = tid + j * THREADS;
        float4 s  = st4[i];
        float4 xv = sx[i];
        float w0 = (s.x > 50.0f) ? 1.0f : 0.0f;
        float w1 = (s.y > 50.0f) ? 1.0f : 0.0f;
        float w2 = (s.z > 50.0f) ? 1.0f : 0.0f;
        float w3 = (s.w > 50.0f) ? 1.0f : 0.0f;
        dot  += w0 * xv.x + w1 * xv.y + w2 * xv.z + w3 * xv.w;
        wsum += w0 + w1 + w2 + w3;
    }

    // Warp reduce
    #pragma unroll
    for (int off = 16; off > 0; off >>= 1) {
        dot  += __shfl_xor_sync(0xFFFFFFFFu, dot,  off);
        wsum += __shfl_xor_sync(0xFFFFFFFFu, wsum, off);
    }
    const int lane = tid & 31;
    const int wid  = tid >> 5;
    if (lane == 0) { warp_dot[wid] = dot; warp_wsum[wid] = wsum; }
    __syncthreads();   // the single barrier: partials published

    // All-thread redundant final reduce + epilogue (pure smem + ALU).
    float d = 0.0f, ws = 0.0f;
    #pragma unroll
    for (int w = 0; w < NWARPS; w++) { d += warp_dot[w]; ws += warp_wsum[w]; }
    const float conn    = fmaxf(ws, 5.0f);
    const float current = d * (15.0f * rsqrtf(conn));
    const float v_mem   = mp_o * 0.85f + current;
    const float spike   = (v_mem >= thr_o) ? 1.0f : 0.0f;
    if (tid == 0) {
        const float new_v = v_mem * (1.0f - spike) * 0.1f;
        const float new_t = fminf(fmaxf(thr_o + (spike - 0.1f) * 0.1f, 2.0f), 15.0f);
        out[o]                    = spike;   // spikes
        out[OUT_FEATURES + o]     = new_v;   // new membrane potential
        out[2 * OUT_FEATURES + o] = new_t;   // new adaptive threshold
    }

    // ---- Phase 2: eligibility-trace update ----
    const float4* tr4 = reinterpret_cast<const float4*>(trace + (size_t)o * IN_FEATURES);
    float4* ot4 = reinterpret_cast<float4*>(out + 3 * (size_t)OUT_FEATURES + (size_t)o * IN_FEATURES);
    #pragma unroll
    for (int j = 0; j < F4_PER_THREAD; j++) {
        const int i = tid + j * THREADS;
        float4 t  = tr4[i];
        float4 xv = sx[i];
        float4 r;
        r.x = fminf(fmaxf(t.x * 0.9f + spike * xv.x, 0.0f), 5.0f);
        r.y = fminf(fmaxf(t.y * 0.9f + spike * xv.y, 0.0f), 5.0f);
        r.z = fminf(fmaxf(t.z * 0.9f + spike * xv.z, 0.0f), 5.0f);
        r.w = fminf(fmaxf(t.w * 0.9f + spike * xv.w, 0.0f), 5.0f);
        __stcs(&ot4[i], r);
    }
}

extern "C" void kernel_launch(void* const* d_in, const int* in_sizes, int n_in,
                              void* d_out, int out_size) {
    const float* x      = (const float*)d_in[0];   // spike_input [8192]
    const float* states = (const float*)d_in[1];   // synapse_states [8192,8192]
    const float* mp     = (const float*)d_in[2];   // membrane_potential [8192]
    const float* thr    = (const float*)d_in[3];   // adaptive_threshold [8192]
    const float* trace  = (const float*)d_in[4];   // eligibility_trace [8192,8192]
    float* out          = (float*)d_out;

    snn_fused_kernel<<<OUT_FEATURES, THREADS>>>(x, states, mp, thr, trace, out);
}